// round 14
// baseline (speedup 1.0000x reference)
#include <cuda_runtime.h>
#include <cuda_bf16.h>

// Problem constants
#define B_SZ 64
#define C_SZ 3
#define H_SZ 512
#define W_SZ 512
#define GRID 4
#define GH (H_SZ / GRID)             // 128 rows per slab
#define NBLK (B_SZ * GRID * C_SZ)    // 768 blocks x 256 threads (best streaming config)

// Scratch: per (b, grid_row, channel, grid_col) partial sums.
// Every slot written exclusively by one block each launch -> no zeroing needed.
__device__ float g_part[B_SZ * GRID * C_SZ * GRID];

// Stage 1: pure streaming reduction (R2's measured-best 31.3us / 80% DRAM).
// Each block reduces one (b, grid_row, channel) slab = 128 rows x 512 floats.
// 8 warps; each warp sweeps 16 rows. Per row (128 float4), lane i loads float4
// positions i, i+32, i+64, i+96 -> grid columns 0..3 (4 private accumulators).
// After publishing its g_part slot (+fence), each block triggers programmatic
// launch completion so stage 2 can begin without waiting for kernel teardown.
__global__ void __launch_bounds__(256) stage1_gridsum(const float* __restrict__ in) {
    const int blk = blockIdx.x;              // [0, 768)
    const int c  = blk % C_SZ;
    const int gr = (blk / C_SZ) % GRID;
    const int b  = blk / (C_SZ * GRID);

    const size_t base_off = ((size_t)(b * C_SZ + c) * H_SZ + (size_t)gr * GH) * W_SZ;
    const float4* __restrict__ base = (const float4*)(in + base_off);
    // rows are 128 float4 wide

    const int warp = threadIdx.x >> 5;
    const int lane = threadIdx.x & 31;

    float a0 = 0.f, a1 = 0.f, a2 = 0.f, a3 = 0.f;

    #pragma unroll 2
    for (int r = warp; r < GH; r += 8) {
        const float4* __restrict__ row = base + (size_t)r * 128;
        float4 v0 = row[lane +  0];   // grid col 0
        float4 v1 = row[lane + 32];   // grid col 1
        float4 v2 = row[lane + 64];   // grid col 2
        float4 v3 = row[lane + 96];   // grid col 3
        a0 += (v0.x + v0.y) + (v0.z + v0.w);
        a1 += (v1.x + v1.y) + (v1.z + v1.w);
        a2 += (v2.x + v2.y) + (v2.z + v2.w);
        a3 += (v3.x + v3.y) + (v3.z + v3.w);
    }

    // Warp tree reduction (deterministic)
    #pragma unroll
    for (int off = 16; off > 0; off >>= 1) {
        a0 += __shfl_down_sync(0xFFFFFFFFu, a0, off);
        a1 += __shfl_down_sync(0xFFFFFFFFu, a1, off);
        a2 += __shfl_down_sync(0xFFFFFFFFu, a2, off);
        a3 += __shfl_down_sync(0xFFFFFFFFu, a3, off);
    }

    __shared__ float s[8][4];
    if (lane == 0) {
        s[warp][0] = a0; s[warp][1] = a1; s[warp][2] = a2; s[warp][3] = a3;
    }
    __syncthreads();

    if (threadIdx.x < 4) {
        const int gc = threadIdx.x;
        float sum = 0.f;
        #pragma unroll
        for (int w = 0; w < 8; ++w) sum += s[w][gc];   // fixed order -> deterministic
        g_part[((b * GRID + gr) * C_SZ + c) * GRID + gc] = sum;
    }
    __syncthreads();   // g_part stores happen-before the fence+trigger

    if (threadIdx.x == 0) {
        __threadfence();   // make this block's g_part slot globally visible
        cudaTriggerProgrammaticLaunchCompletion();
    }
}

// Stage 2 (PDL consumer): launch overlaps stage 1; gridsync gates g_part reads.
// One thread per batch: channel-sum -> 3x3 window sums -> argmax -> (row,col).
__global__ void __launch_bounds__(64) stage2_select(float* __restrict__ out) {
    cudaGridDependencySynchronize();   // wait for all stage-1 CTAs' triggers

    const int bb = threadIdx.x;        // blockDim.x == B_SZ == 64
    float cell[GRID][GRID];
    #pragma unroll
    for (int gr2 = 0; gr2 < GRID; ++gr2) {
        #pragma unroll
        for (int gc = 0; gc < GRID; ++gc) {
            float sum = 0.f;
            #pragma unroll
            for (int cc = 0; cc < C_SZ; ++cc)
                sum += g_part[((bb * GRID + gr2) * C_SZ + cc) * GRID + gc];
            cell[gr2][gc] = sum;
        }
    }

    float w[4];
    #pragma unroll
    for (int wr = 0; wr < 2; ++wr) {
        #pragma unroll
        for (int wc = 0; wc < 2; ++wc) {
            float sum = 0.f;
            #pragma unroll
            for (int i = 0; i < 3; ++i)
                #pragma unroll
                for (int j = 0; j < 3; ++j)
                    sum += cell[wr + i][wc + j];
            w[wr * 2 + wc] = sum;
        }
    }

    int best = 0;
    float bv = w[0];
    #pragma unroll
    for (int i = 1; i < 4; ++i) {
        if (w[i] > bv) { bv = w[i]; best = i; }   // strict > = first-index tie-break
    }

    out[bb * 2 + 0] = (float)(best >> 1);   // row
    out[bb * 2 + 1] = (float)(best & 1);    // col
}

extern "C" void kernel_launch(void* const* d_in, const int* in_sizes, int n_in,
                              void* d_out, int out_size) {
    const float* sampling_map = (const float*)d_in[0];
    float* out = (float*)d_out;

    stage1_gridsum<<<NBLK, 256>>>(sampling_map);

    // Stage 2 with Programmatic Dependent Launch: its launch/prologue overlap
    // stage 1; cudaGridDependencySynchronize() inside provides the ordering.
    cudaLaunchConfig_t cfg = {};
    cfg.gridDim  = dim3(1, 1, 1);
    cfg.blockDim = dim3(64, 1, 1);
    cfg.dynamicSmemBytes = 0;
    cfg.stream = 0;
    cudaLaunchAttribute attr[1];
    attr[0].id = cudaLaunchAttributeProgrammaticStreamSerialization;
    attr[0].val.programmaticStreamSerializationAllowed = 1;
    cfg.attrs = attr;
    cfg.numAttrs = 1;
    cudaLaunchKernelEx(&cfg, stage2_select, out);
}

// round 15
// speedup vs baseline: 1.0438x; 1.0438x over previous
#include <cuda_runtime.h>
#include <cuda_bf16.h>

// Problem constants
#define B_SZ 64
#define C_SZ 3
#define H_SZ 512
#define W_SZ 512
#define GRID 4
#define GH (H_SZ / GRID)             // 128 rows per slab
#define NBLK (B_SZ * GRID * C_SZ)    // 768 blocks x 256 threads
#define GRP 12                       // blocks per batch (GRID * C_SZ)
#define PAD 32                       // 128B padding between group counters

// Scratch: per (b, grid_row, channel, grid_col) partial sums.
// Every slot written exclusively by one block each launch -> no zeroing needed.
__device__ float g_part[B_SZ * GRID * C_SZ * GRID];
// One counter per batch, 128B apart (distinct LTS lines, parallel drains).
// Each is reset to 0 by its group winner every launch.
__device__ unsigned int g_cnt[B_SZ * PAD];

// Fully distributed epilogue: NO global rendezvous. The 12th finishing block
// of each batch performs that batch's selection inline, concurrently with
// other batches still streaming. Kernel end = slowest block + tiny epilogue.
__global__ void __launch_bounds__(256) region_select_dist(
    const float* __restrict__ in, float* __restrict__ out) {
    const int blk = blockIdx.x;              // [0, 768)
    const int c  = blk % C_SZ;
    const int gr = (blk / C_SZ) % GRID;
    const int b  = blk / (C_SZ * GRID);

    const size_t base_off = ((size_t)(b * C_SZ + c) * H_SZ + (size_t)gr * GH) * W_SZ;
    const float4* __restrict__ base = (const float4*)(in + base_off);
    // rows are 128 float4 wide

    const int warp = threadIdx.x >> 5;
    const int lane = threadIdx.x & 31;

    float a0 = 0.f, a1 = 0.f, a2 = 0.f, a3 = 0.f;

    #pragma unroll 2
    for (int r = warp; r < GH; r += 8) {
        const float4* __restrict__ row = base + (size_t)r * 128;
        float4 v0 = row[lane +  0];   // grid col 0
        float4 v1 = row[lane + 32];   // grid col 1
        float4 v2 = row[lane + 64];   // grid col 2
        float4 v3 = row[lane + 96];   // grid col 3
        a0 += (v0.x + v0.y) + (v0.z + v0.w);
        a1 += (v1.x + v1.y) + (v1.z + v1.w);
        a2 += (v2.x + v2.y) + (v2.z + v2.w);
        a3 += (v3.x + v3.y) + (v3.z + v3.w);
    }

    // Warp tree reduction (deterministic)
    #pragma unroll
    for (int off = 16; off > 0; off >>= 1) {
        a0 += __shfl_down_sync(0xFFFFFFFFu, a0, off);
        a1 += __shfl_down_sync(0xFFFFFFFFu, a1, off);
        a2 += __shfl_down_sync(0xFFFFFFFFu, a2, off);
        a3 += __shfl_down_sync(0xFFFFFFFFu, a3, off);
    }

    __shared__ float s[8][4];
    if (lane == 0) {
        s[warp][0] = a0; s[warp][1] = a1; s[warp][2] = a2; s[warp][3] = a3;
    }
    __syncthreads();

    if (threadIdx.x < 4) {
        const int gc = threadIdx.x;
        float sum = 0.f;
        #pragma unroll
        for (int w = 0; w < 8; ++w) sum += s[w][gc];   // fixed order -> deterministic
        g_part[((b * GRID + gr) * C_SZ + c) * GRID + gc] = sum;
    }
    __syncthreads();   // this block's g_part stores happen-before thread 0's fence

    if (threadIdx.x != 0) return;   // only thread 0 continues

    __threadfence();                                   // release this block's slot
    unsigned int old = atomicAdd(&g_cnt[b * PAD], 1u); // per-batch counter
    if (old != (unsigned)(GRP - 1)) return;            // not the group winner

    // ---- Group winner: selection for batch b (single thread, ~48 L2 loads) ----
    g_cnt[b * PAD] = 0;   // reset own counter for next graph replay
    __threadfence();      // acquire: all 12 group slots now visible

    const float* __restrict__ gp = &g_part[b * (GRID * C_SZ * GRID)];
    float cell[GRID][GRID];
    #pragma unroll
    for (int gr2 = 0; gr2 < GRID; ++gr2) {
        #pragma unroll
        for (int gc = 0; gc < GRID; ++gc) {
            float sum = 0.f;
            #pragma unroll
            for (int cc = 0; cc < C_SZ; ++cc)
                sum += gp[(gr2 * C_SZ + cc) * GRID + gc];   // fixed order
            cell[gr2][gc] = sum;
        }
    }

    float w[4];
    #pragma unroll
    for (int wr = 0; wr < 2; ++wr) {
        #pragma unroll
        for (int wc = 0; wc < 2; ++wc) {
            float sum = 0.f;
            #pragma unroll
            for (int i = 0; i < 3; ++i)
                #pragma unroll
                for (int j = 0; j < 3; ++j)
                    sum += cell[wr + i][wc + j];
            w[wr * 2 + wc] = sum;
        }
    }

    int best = 0;
    float bv = w[0];
    #pragma unroll
    for (int i = 1; i < 4; ++i) {
        if (w[i] > bv) { bv = w[i]; best = i; }   // strict > = first-index tie-break
    }

    out[b * 2 + 0] = (float)(best >> 1);   // row
    out[b * 2 + 1] = (float)(best & 1);    // col
}

extern "C" void kernel_launch(void* const* d_in, const int* in_sizes, int n_in,
                              void* d_out, int out_size) {
    const float* sampling_map = (const float*)d_in[0];
    float* out = (float*)d_out;

    region_select_dist<<<NBLK, 256>>>(sampling_map, out);
}